// round 16
// baseline (speedup 1.0000x reference)
#include <cuda_runtime.h>
#include <math.h>
#include <stdint.h>

#define VOCAB 32768
#define D 512
#define NB 3
#define NF 3
#define T 4
#define NJ 36   // T*NF*NB
#define P1_BLOCKS 72
#define P3_GRID 132        // 4 Jacobi blocks + 128 worker blocks
#define KP_BLOCKS 256
#define JAC_SWEEPS 6

// ---------------- scratch (device globals; no allocation) ----------------
__device__ float g_part[2*NF*NB*8*D];   // double-buffered by t-parity
__device__ float g_U[NJ*D];             // [t][f][n][d], j = t*9+f*3+n
__device__ float g_Ut[D*40];            // transposed U [d][j], cols 36..39 stay 0
__device__ float g_w[NJ];               // bubble weights [t][f][n]
__device__ float g_Z[T*NF*VOCAB];       // zf = born(rho_f) logits
__device__ float g_red5[T*KP_BLOCKS*12];
__device__ float g_c[NJ];               // meta coeffs c = weights_f * w_fn
__device__ float g_wt[T*NF];            // meta foam weights
__device__ float g_invSf[T*NF];
__device__ float g_As[T*81];            // meta matrices for Jacobi
__device__ float g_red7[T*32*2];
__device__ unsigned g_bar_count;        // phase1 barrier (self-resetting)
__device__ unsigned g_bar_epoch;
__device__ unsigned g_tick;             // k_P ticket (self-resetting)
__device__ unsigned g_bc2, g_be2;       // phase3 barrier

// Brent-Luk round-robin pairs for 9x9 Jacobi
__constant__ int c_pairs[9][4][2] = {
    {{1,8},{2,7},{3,6},{4,5}},
    {{0,1},{2,8},{3,7},{4,6}},
    {{0,2},{3,8},{4,7},{5,6}},
    {{0,3},{1,2},{4,8},{5,7}},
    {{0,4},{1,3},{5,8},{6,7}},
    {{0,5},{1,4},{2,3},{6,8}},
    {{0,6},{1,5},{2,4},{7,8}},
    {{0,7},{1,6},{2,5},{3,4}},
    {{0,8},{1,7},{2,6},{3,5}},
};

// ---------------- helpers ----------------
__device__ __forceinline__ void barrierOn(unsigned* cnt, unsigned* ep, unsigned n) {
    __threadfence();
    __syncthreads();
    if (threadIdx.x == 0) {
        unsigned e0 = *(volatile unsigned*)ep;
        unsigned my = atomicAdd(cnt, 1u);
        if (my == n - 1u) {
            *cnt = 0u;
            __threadfence();
            atomicAdd(ep, 1u);
        } else {
            while (*(volatile unsigned*)ep == e0) { __nanosleep(64); }
        }
    }
    __syncthreads();
}

__device__ __forceinline__ void blockReduce3(float a, float b, float c,
                                             float* sh48, float* res) {
    #pragma unroll
    for (int o = 16; o > 0; o >>= 1) {
        a += __shfl_down_sync(0xffffffffu, a, o);
        b += __shfl_down_sync(0xffffffffu, b, o);
        c += __shfl_down_sync(0xffffffffu, c, o);
    }
    int lane = threadIdx.x & 31, wid = threadIdx.x >> 5;
    if (lane == 0) { sh48[wid*3+0] = a; sh48[wid*3+1] = b; sh48[wid*3+2] = c; }
    __syncthreads();
    if (threadIdx.x < 3) {
        float s = 0.f;
        #pragma unroll
        for (int i = 0; i < 16; i++) s += sh48[i*3 + threadIdx.x];
        res[threadIdx.x] = s;
    }
    __syncthreads();
}

// tf32 MMA m16n8k8: D += A(16x8) * B(8x8)
__device__ __forceinline__ void mma_tf32(float* d, const uint32_t* a,
                                         uint32_t b0, uint32_t b1) {
    asm volatile(
        "mma.sync.aligned.m16n8k8.row.col.f32.tf32.tf32.f32 "
        "{%0,%1,%2,%3}, {%4,%5,%6,%7}, {%8,%9}, {%0,%1,%2,%3};"
        : "+f"(d[0]), "+f"(d[1]), "+f"(d[2]), "+f"(d[3])
        : "r"(a[0]), "r"(a[1]), "r"(a[2]), "r"(a[3]), "r"(b0), "r"(b1));
}

__device__ __forceinline__ void cp16(float* dst_smem, const float* src) {
    uint32_t d = (uint32_t)__cvta_generic_to_shared(dst_smem);
    asm volatile("cp.async.ca.shared.global [%0], [%1], 16;" :: "r"(d), "l"(src));
}

// ---------------- phase 1: foam recurrence (72 blocks, 1 barrier/step) ----------------
__global__ void __launch_bounds__(512) k_phase1(
        const int* __restrict__ tokens, const float* __restrict__ E,
        const float* __restrict__ Ws, const float* __restrict__ mdb,
        const float* __restrict__ nsens) {
    int b = blockIdx.x;
    int m = b >> 3, c = b & 7, f = m / NB;
    int e = threadIdx.x;
    bool writer = ((b % 24) == 0);     // blocks 0,24,48 own f=0,1,2 outputs
    __shared__ float xs[64];
    __shared__ float sh48[48];
    __shared__ float res[3];
    __shared__ float bcast[8];

    float w[64];
    const float* Wp = Ws + ((size_t)m*D + c*64)*D + e;
    #pragma unroll
    for (int i = 0; i < 64; i++) w[i] = Wp[(size_t)i*D];

    float mem0 = 0.f, mem1 = 0.f, mem2 = 0.f;
    float decay = 0.f;
    float sens = fabsf(nsens[0]);
    float mdb0 = mdb[0];
    float xin_e = E[(size_t)tokens[0]*D + e];

    for (int t = 0; t < T; t++) {
        if ((e >> 6) == c) xs[e & 63] = xin_e;
        __syncthreads();
        float acc = 0.f;
        #pragma unroll
        for (int i = 0; i < 64; i++) acc = fmaf(xs[i], w[i], acc);
        int buf = (t & 1) * (NF*NB*8*D);
        g_part[buf + (m*8 + c)*D + e] = acc;
        __syncthreads();
        barrierOn(&g_bar_count, &g_bar_epoch, P1_BLOCKS);

        if (t == 0) {
            float a = mdb0 - sens;
            decay = 1.f / (1.f + expf(-a));
        }
        float s0 = 0.f, s1 = 0.f, s2 = 0.f;
        #pragma unroll
        for (int cc = 0; cc < 8; cc++) {
            s0 += g_part[buf + ((f*NB + 0)*8 + cc)*D + e];
            s1 += g_part[buf + ((f*NB + 1)*8 + cc)*D + e];
            s2 += g_part[buf + ((f*NB + 2)*8 + cc)*D + e];
        }
        #pragma unroll
        for (int it = 0; it < 3; it++) {
            float mn = (s0 + s1 + s2) * (1.0f/3.0f);
            s0 += 0.3f * (mn - s0);
            s1 += 0.3f * (mn - s1);
            s2 += 0.3f * (mn - s2);
        }
        if (writer) {
            blockReduce3(s0*s0, s1*s1, s2*s2, sh48, res);
            if (e == 0) {
                float nr[3] = {sqrtf(res[0]), sqrtf(res[1]), sqrtf(res[2])};
                float mx = fmaxf(fmaxf(2.f*nr[0], 2.f*nr[1]), 2.f*nr[2]);
                float ex[3], se = 0.f;
                #pragma unroll
                for (int n = 0; n < 3; n++) { ex[n] = expf(2.f*nr[n] - mx); se += ex[n]; }
                #pragma unroll
                for (int n = 0; n < 3; n++) {
                    g_w[(t*NF + f)*NB + n] = ex[n] / se;
                    bcast[n] = 1.f / (nr[n] + 1e-10f);
                }
            }
            __syncthreads();
            float u0 = s0 * bcast[0], u1 = s1 * bcast[1], u2 = s2 * bcast[2];
            g_U[((t*NF + f)*NB + 0)*D + e] = u0;
            g_U[((t*NF + f)*NB + 1)*D + e] = u1;
            g_U[((t*NF + f)*NB + 2)*D + e] = u2;
            int jb = t*9 + f*3;
            g_Ut[e*40 + jb + 0] = u0;
            g_Ut[e*40 + jb + 1] = u1;
            g_Ut[e*40 + jb + 2] = u2;
        }
        mem0 = decay*mem0 + (1.f - decay)*s0;
        mem1 = decay*mem1 + (1.f - decay)*s1;
        mem2 = decay*mem2 + (1.f - decay)*s2;
        if (t < T-1) {
            float x = E[(size_t)tokens[t+1]*D + e];
            float mm = (mem0 + mem1 + mem2) * (1.0f/3.0f);
            blockReduce3(mm*mm, x*mm, x*x, sh48, res);
            if (e == 0) {
                float mn = sqrtf(res[0]) + 1e-10f;
                float xn = sqrtf(res[2]) + 1e-10f;
                float nov = (mn > 1e-8f) ? (1.f - res[1]/(xn*mn)) : 1.f;
                float a = mdb0 - sens * nov;
                bcast[4] = 1.f / (1.f + expf(-a));
            }
            __syncthreads();
            decay = bcast[4];
            xin_e = x + decay*mm;
        }
    }
}

// ---------------- phase 2: tf32 GEMM + ticket epilogue (meta weights) ----------------
// 256 blocks x 256 threads. Block: 128 v x 40 j x K=512 in 8 superchunks of 64.
// LAST block (atomic ticket) computes the meta-weight reductions while L2 is hot.
__global__ void __launch_bounds__(256) k_P(const float* __restrict__ E,
                                           const float* __restrict__ mt,
                                           float* __restrict__ out_w) {
    __shared__ float sbuf[22528];
    __shared__ float wsh[36];
    __shared__ float wred[8][12];
    float* Ps = sbuf;
    int tid = threadIdx.x;
    int wid = tid >> 5, lane = tid & 31;
    int v0 = blockIdx.x * 128;
    if (tid < 36) wsh[tid] = g_w[tid];

    float acc[5][4];
    #pragma unroll
    for (int nt = 0; nt < 5; nt++)
        #pragma unroll
        for (int q = 0; q < 4; q++) acc[nt][q] = 0.f;

    int mbase = wid * 16;
    int arow = lane >> 2, acol = lane & 3;
    int brow = lane & 3,  bcol = lane >> 2;

    auto stage = [&](int sc, int s) {
        int k0 = sc * 64;
        float* Es = sbuf + s*8704;
        float* Us = sbuf + 17408 + s*2560;
        #pragma unroll
        for (int it = 0; it < 8; it++) {
            int flat = it*256 + tid;
            int row = flat >> 4, seg = flat & 15;
            cp16(&Es[row*68 + seg*4], E + (size_t)(v0+row)*D + k0 + seg*4);
        }
        #pragma unroll
        for (int it = 0; it < 3; it++) {
            int flat = it*256 + tid;
            if (flat < 640) {
                int dd = flat / 10, q = flat - dd*10;
                cp16(&Us[dd*40 + q*4], g_Ut + (size_t)(k0+dd)*40 + q*4);
            }
        }
    };

    stage(0, 0);
    asm volatile("cp.async.commit_group;");

    for (int sc = 0; sc < 8; sc++) {
        if (sc < 7) {
            stage(sc+1, (sc+1) & 1);
            asm volatile("cp.async.commit_group;");
            asm volatile("cp.async.wait_group 1;" ::: "memory");
        } else {
            asm volatile("cp.async.wait_group 0;" ::: "memory");
        }
        __syncthreads();
        const uint32_t* EsU = (const uint32_t*)(sbuf + (sc & 1)*8704);
        const uint32_t* UsU = (const uint32_t*)(sbuf + 17408 + (sc & 1)*2560);
        #pragma unroll
        for (int ks = 0; ks < 8; ks++) {
            int kb = ks * 8;
            uint32_t a[4];
            int r = mbase + arow;
            a[0] = EsU[r*68 + kb + acol];
            a[1] = EsU[(r+8)*68 + kb + acol];
            a[2] = EsU[r*68 + kb + acol + 4];
            a[3] = EsU[(r+8)*68 + kb + acol + 4];
            #pragma unroll
            for (int nt = 0; nt < 5; nt++) {
                uint32_t b0 = UsU[(kb + brow)*40 + nt*8 + bcol];
                uint32_t b1 = UsU[(kb + brow + 4)*40 + nt*8 + bcol];
                mma_tf32(acc[nt], a, b0, b1);
            }
        }
        __syncthreads();
    }

    // scatter P fragments to smem: Ps[j][v], stride 132
    #pragma unroll
    for (int nt = 0; nt < 5; nt++) {
        int vr = mbase + arow;
        int jc = nt*8 + acol*2;
        Ps[jc*132 + vr]         = acc[nt][0];
        Ps[(jc+1)*132 + vr]     = acc[nt][1];
        Ps[jc*132 + vr + 8]     = acc[nt][2];
        Ps[(jc+1)*132 + vr + 8] = acc[nt][3];
    }
    __syncthreads();
    // epilogue: warp -> (t = wid>>1, half = wid&1), 2 v per lane
    {
        int t = wid >> 1, half = wid & 1;
        int vb = half*64 + lane*2;
        float vals[12];
        #pragma unroll
        for (int k = 0; k < 12; k++) vals[k] = 0.f;
        float ef[3][2];
        #pragma unroll
        for (int f = 0; f < 3; f++) {
            float z0 = 0.f, z1 = 0.f;
            #pragma unroll
            for (int n = 0; n < 3; n++) {
                int j = t*9 + f*3 + n;
                float2 p = *(const float2*)&Ps[j*132 + vb];
                float ww = wsh[j];
                z0 = fmaf(ww*p.x, p.x, z0);
                z1 = fmaf(ww*p.y, p.y, z1);
            }
            *(float2*)&g_Z[((size_t)(t*3+f))*VOCAB + v0 + vb] = make_float2(z0, z1);
            float e0 = __expf(z0), e1 = __expf(z1);
            ef[f][0] = e0; ef[f][1] = e1;
            vals[f]   = e0 + e1;
            vals[3+f] = e0*z0 + e1*z1;
        }
        #pragma unroll
        for (int q = 0; q < 2; q++) {
            vals[6]  += ef[0][q]*ef[0][q];
            vals[7]  += ef[0][q]*ef[1][q];
            vals[8]  += ef[0][q]*ef[2][q];
            vals[9]  += ef[1][q]*ef[1][q];
            vals[10] += ef[1][q]*ef[2][q];
            vals[11] += ef[2][q]*ef[2][q];
        }
        #pragma unroll
        for (int k = 0; k < 12; k++) {
            #pragma unroll
            for (int o = 16; o > 0; o >>= 1)
                vals[k] += __shfl_down_sync(0xffffffffu, vals[k], o);
        }
        if (lane == 0) {
            #pragma unroll
            for (int k = 0; k < 12; k++) wred[wid][k] = vals[k];
        }
    }
    __syncthreads();
    if (tid < 48) {
        int t2 = tid / 12, k = tid % 12;
        g_red5[(t2*KP_BLOCKS + blockIdx.x)*12 + k] = wred[t2*2][k] + wred[t2*2+1][k];
    }

    // ---- ticket: last block computes meta weights + As (L2-hot) ----
    __threadfence();
    __syncthreads();
    __shared__ unsigned sLast;
    if (tid == 0) {
        unsigned old = atomicAdd(&g_tick, 1u);
        sLast = (old == KP_BLOCKS - 1u) ? 1u : 0u;
        if (sLast) g_tick = 0u;
    }
    __syncthreads();
    if (!sLast) return;

    __shared__ float fred[48];     // [t][12]
    __shared__ float fgram[180];   // [t][45]
    __shared__ float fc9[36];      // [t][9]
    for (int job = wid; job < 48; job += 8) {
        int t = job / 12, k = job % 12;
        float s = 0.f;
        for (int i = lane; i < KP_BLOCKS; i += 32)
            s += g_red5[(t*KP_BLOCKS + i)*12 + k];
        #pragma unroll
        for (int o = 16; o > 0; o >>= 1) s += __shfl_down_sync(0xffffffffu, s, o);
        if (lane == 0) fred[job] = s;
    }
    for (int job = wid; job < 180; job += 8) {
        int t = job / 45, pr = job % 45;
        int i = 0, rem = pr;
        while (rem > i) { rem -= (i + 1); i++; }
        int j = rem;
        float s = 0.f;
        const float* ui = g_U + (size_t)(t*9 + i)*D;
        const float* uj = g_U + (size_t)(t*9 + j)*D;
        for (int e = lane; e < D; e += 32) s += ui[e]*uj[e];
        #pragma unroll
        for (int o = 16; o > 0; o >>= 1) s += __shfl_down_sync(0xffffffffu, s, o);
        if (lane == 0) fgram[job] = s;
    }
    __syncthreads();
    if (tid < 4) {
        int t = tid;
        const float MAXENT = logf(32768.0f);
        const float* red = fred + t*12;
        float S[3]  = { red[0], red[1], red[2] };
        float Tm[3] = { red[3], red[4], red[5] };
        float G00 = red[6], G01 = red[7], G02 = red[8];
        float G11 = red[9], G12 = red[10], G22 = red[11];
        float H[3], conc[3], np[3];
        #pragma unroll
        for (int f = 0; f < 3; f++) {
            H[f] = __logf(S[f]) - __fdividef(Tm[f], S[f]);
            conc[f] = 1.f - H[f]/MAXENT;
        }
        np[0] = __fdividef(__fsqrt_rn(G00), S[0]) + 1e-10f;
        np[1] = __fdividef(__fsqrt_rn(G11), S[1]) + 1e-10f;
        np[2] = __fdividef(__fsqrt_rn(G22), S[2]) + 1e-10f;
        float A01 = __fdividef(__fdividef(G01, S[0]*S[1]), np[0]*np[1]);
        float A02 = __fdividef(__fdividef(G02, S[0]*S[2]), np[0]*np[2]);
        float A12 = __fdividef(__fdividef(G12, S[1]*S[2]), np[1]*np[2]);
        float agree[3] = { 0.5f*(A01+A02), 0.5f*(A01+A12), 0.5f*(A02+A12) };
        float temp = fmaxf(fabsf(mt[0]), 0.01f);
        float l[3], mx = -1e30f;
        #pragma unroll
        for (int f = 0; f < 3; f++) {
            l[f] = __fdividef(conc[f]*agree[f], temp);
            mx = fmaxf(mx, l[f]);
        }
        float ex[3], se = 0.f;
        #pragma unroll
        for (int f = 0; f < 3; f++) { ex[f] = __expf(l[f]-mx); se += ex[f]; }
        float invse = __fdividef(1.f, se);
        #pragma unroll
        for (int f = 0; f < 3; f++) {
            float wt = ex[f]*invse;
            out_w[t*3 + f] = wt;
            g_wt[t*3 + f] = wt;
            g_invSf[t*3 + f] = __fdividef(1.f, S[f]);
            #pragma unroll
            for (int n = 0; n < 3; n++) {
                float cv = wt * g_w[(t*3+f)*3 + n];
                g_c[t*9 + f*3 + n] = cv;
                fc9[t*9 + f*3 + n] = cv;
            }
        }
    }
    __syncthreads();
    for (int idx = tid; idx < 324; idx += 256) {
        int t = idx / 81, ij = idx % 81;
        int i = ij / 9, j = ij % 9;
        int a = i > j ? i : j, bb = i > j ? j : i;
        g_As[idx] = __fsqrt_rn(fc9[t*9+i]*fc9[t*9+j]) * fgram[t*45 + a*(a+1)/2 + bb];
    }
}

// ---------------- phase 3: (Jacobi blocks 0..3) || (workers 4..131), ONE barrier ----------------
__global__ void __launch_bounds__(512) k_phase3(
        float* __restrict__ out_tok, float* __restrict__ out_d,
        float* __restrict__ out_rho, float* __restrict__ out_S,
        float* __restrict__ out_H, float* __restrict__ out_F) {
    int b = blockIdx.x;
    int tid = threadIdx.x;
    int w = tid >> 5, lane = tid & 31;

    if (b < T) {
        // ===== Jacobi block: eigen from g_As (concurrent with workers' stage B) =====
        int t = b;
        __shared__ float As[81];
        __shared__ float csh[4], ssh[4];
        __shared__ float sSr;
        if (tid < 81) As[tid] = g_As[t*81 + tid];
        __syncthreads();
        if (w == 0) {
            for (int round = 0; round < 9*JAC_SWEEPS; round++) {
                int r = round % 9;
                if (lane < 4) {
                    int p = c_pairs[r][lane][0], q = c_pairs[r][lane][1];
                    float apq = As[p*9+q];
                    float cc = 1.f, ss = 0.f;
                    if (fabsf(apq) > 1e-20f) {
                        float theta = __fdividef(As[q*9+q] - As[p*9+p], 2.f*apq);
                        float tt = __fdividef(copysignf(1.f, theta),
                                   fabsf(theta) + __fsqrt_rn(theta*theta + 1.f));
                        cc = rsqrtf(tt*tt + 1.f);
                        ss = tt*cc;
                    }
                    csh[lane] = cc; ssh[lane] = ss;
                }
                __syncwarp();
                {
                    int k = lane & 3, i = lane >> 2;
                    int p = c_pairs[r][k][0], q = c_pairs[r][k][1];
                    float cc = csh[k], ss = ssh[k];
                    float aip = As[i*9+p], aiq = As[i*9+q];
                    As[i*9+p] = cc*aip - ss*aiq;
                    As[i*9+q] = ss*aip + cc*aiq;
                    if (lane < 4) {
                        int p2 = c_pairs[r][lane][0], q2 = c_pairs[r][lane][1];
                        float c2 = csh[lane], s2 = ssh[lane];
                        float a1 = As[8*9+p2], a2 = As[8*9+q2];
                        As[8*9+p2] = c2*a1 - s2*a2;
                        As[8*9+q2] = s2*a1 + c2*a2;
                    }
                }
                __syncwarp();
                {
                    int k = lane & 3, j = lane >> 2;
                    int p = c_pairs[r][k][0], q = c_pairs[r][k][1];
                    float cc = csh[k], ss = ssh[k];
                    float apj = As[p*9+j], aqj = As[q*9+j];
                    As[p*9+j] = cc*apj - ss*aqj;
                    As[q*9+j] = ss*apj + cc*aqj;
                    if (lane < 4) {
                        int p2 = c_pairs[r][lane][0], q2 = c_pairs[r][lane][1];
                        float c2 = csh[lane], s2 = ssh[lane];
                        float a1 = As[p2*9+8], a2 = As[q2*9+8];
                        As[p2*9+8] = c2*a1 - s2*a2;
                        As[q2*9+8] = s2*a1 + c2*a2;
                    }
                }
                __syncwarp();
            }
        }
        __syncthreads();
        if (tid == 0) {
            float lam[9], sum = 503.0f * 1e-12f;
            for (int i = 0; i < 9; i++) { lam[i] = fmaxf(As[i*9+i], 1e-12f); sum += lam[i]; }
            float inv = __fdividef(1.f, sum), Sr = 0.f;
            for (int i = 0; i < 9; i++) {
                float pp = lam[i]*inv;
                Sr -= pp * fmaxf(__logf(pp), -100.f);
            }
            float pz = 1e-12f*inv;
            Sr -= 503.f * pz * fmaxf(__logf(pz), -100.f);
            out_S[t] = Sr;
            sSr = Sr;
        }
        barrierOn(&g_bc2, &g_be2, P3_GRID);   // workers' g_red7 complete
        if (tid == 0) {
            float S = 0.f, Tm = 0.f;
            for (int i = 0; i < 32; i++) {
                S  += g_red7[(t*32 + i)*2 + 0];
                Tm += g_red7[(t*32 + i)*2 + 1];
            }
            float H = __logf(S) - __fdividef(Tm, S);
            out_H[t] = H;
            out_F[t] = H - sSr;
        }
    } else {
        // ===== workers: stage B -> barrier -> stage C =====
        __shared__ float sh6[6];
        __shared__ float wredB[32];
        __shared__ float sred[2];
        __shared__ float Us[9][512];
        __shared__ float cs[9];
        int wk = b - T;
        int t = wk >> 5;
        int vblock = wk & 31;
        int v = vblock * 1024 + tid * 2;
        if (tid < 3) {
            sh6[tid]   = g_wt[t*3 + tid];
            sh6[3+tid] = g_invSf[t*3 + tid];
        }
        __syncthreads();
        float z0 = 0.f, z1 = 0.f;
        #pragma unroll
        for (int f = 0; f < 3; f++) {
            size_t idx = ((size_t)(t*3+f))*VOCAB + v;
            float2 zf = *(const float2*)&g_Z[idx];
            float wf = sh6[f], isf = sh6[3+f];
            z0 = fmaf(wf, zf.x, z0);
            z1 = fmaf(wf, zf.y, z1);
            *(float2*)&out_d[idx] = make_float2(__expf(zf.x)*isf, __expf(zf.y)*isf);
        }
        float e0 = __expf(z0), e1 = __expf(z1);   // kept across barrier
        float r0 = e0 + e1;
        float r1 = e0*z0 + e1*z1;
        #pragma unroll
        for (int o = 16; o > 0; o >>= 1) {
            r0 += __shfl_down_sync(0xffffffffu, r0, o);
            r1 += __shfl_down_sync(0xffffffffu, r1, o);
        }
        if (lane == 0) { wredB[w*2] = r0; wredB[w*2+1] = r1; }
        __syncthreads();
        if (tid < 2) {
            float s = 0.f;
            #pragma unroll
            for (int w2 = 0; w2 < 16; w2++) s += wredB[w2*2 + tid];
            g_red7[(t*32 + vblock)*2 + tid] = s;
        }
        barrierOn(&g_bc2, &g_be2, P3_GRID);

        // stage C
        if (tid < 64) {
            int k = tid >> 5, i = tid & 31;
            float val = g_red7[(t*32 + i)*2 + k];
            #pragma unroll
            for (int o = 16; o > 0; o >>= 1) val += __shfl_down_sync(0xffffffffu, val, o);
            if (i == 0) sred[k] = val;
        }
        #pragma unroll
        for (int k = 0; k < 9; k++) Us[k][tid] = g_U[(size_t)(t*9 + k)*D + tid];
        if (tid < 9) cs[tid] = g_c[t*9 + tid];
        __syncthreads();
        float sInv = __fdividef(1.f, sred[0]);
        *(float2*)&out_tok[(size_t)t*VOCAB + v] = make_float2(e0*sInv, e1*sInv);
        int i0 = vblock * 16;
        #pragma unroll
        for (int ii = 0; ii < 16; ii++) {
            int i = i0 + ii;
            float a = 0.f;
            #pragma unroll
            for (int k = 0; k < 9; k++) a = fmaf(cs[k]*Us[k][i], Us[k][tid], a);
            out_rho[((size_t)t*D + i)*D + tid] = a;
        }
    }
}

// ---------------- launch ----------------
extern "C" void kernel_launch(void* const* d_in, const int* in_sizes, int n_in,
                              void* d_out, int out_size) {
    (void)in_sizes; (void)n_in; (void)out_size;
    const int*   tokens = (const int*)d_in[0];
    const float* E      = (const float*)d_in[1];
    const float* Ws     = (const float*)d_in[2];
    const float* mt     = (const float*)d_in[3];
    const float* mdb    = (const float*)d_in[4];
    const float* ns     = (const float*)d_in[5];

    float* out     = (float*)d_out;
    float* out_tok = out;                         // [4, 32768]
    float* out_rho = out_tok + T*VOCAB;           // [4, 512, 512]
    float* out_w   = out_rho + (size_t)T*D*D;     // [4, 3]
    float* out_S   = out_w + T*NF;                // [4]
    float* out_H   = out_S + T;                   // [4]
    float* out_F   = out_H + T;                   // [4]
    float* out_d   = out_F + T;                   // [4, 3, 32768]

    k_phase1<<<P1_BLOCKS, D>>>(tokens, E, Ws, mdb, ns);
    k_P<<<KP_BLOCKS, 256>>>(E, mt, out_w);
    k_phase3<<<P3_GRID, 512>>>(out_tok, out_d, out_rho, out_S, out_H, out_F);
}

// round 17
// speedup vs baseline: 1.0941x; 1.0941x over previous
#include <cuda_runtime.h>
#include <math.h>
#include <stdint.h>

#define VOCAB 32768
#define D 512
#define NB 3
#define NF 3
#define T 4
#define NJ 36   // T*NF*NB
#define P1_BLOCKS 72       // phase1 participants
#define P1_GRID 148        // padded grid (>=148 to avoid low-grid issue throttle)
#define P3_PART 132        // 4 Jacobi blocks + 128 worker blocks
#define P3_GRID 148        // padded grid
#define P3_WORKERS 128
#define KP_BLOCKS 256
#define JAC_SWEEPS 6

// ---------------- scratch (device globals; no allocation) ----------------
__device__ float g_part[2*NF*NB*8*D];   // double-buffered by t-parity
__device__ float g_U[NJ*D];             // [t][f][n][d], j = t*9+f*3+n
__device__ float g_Ut[D*40];            // transposed U [d][j], cols 36..39 stay 0
__device__ float g_w[NJ];               // bubble weights [t][f][n]
__device__ float g_Z[T*NF*VOCAB];       // zf = born(rho_f) logits
__device__ float g_red5[T*KP_BLOCKS*12];
__device__ float g_c[NJ];               // meta coeffs c = weights_f * w_fn
__device__ float g_wt[T*NF];            // meta foam weights
__device__ float g_invSf[T*NF];
__device__ float g_red7[T*32*2];
__device__ unsigned g_bar_count;        // zero-init; self-resetting
__device__ unsigned g_bar_epoch;        // monotonic across replays
__device__ unsigned g_bc2;              // worker-only barrier
__device__ unsigned g_be2;

// Brent-Luk round-robin pairs for 9x9 Jacobi
__constant__ int c_pairs[9][4][2] = {
    {{1,8},{2,7},{3,6},{4,5}},
    {{0,1},{2,8},{3,7},{4,6}},
    {{0,2},{3,8},{4,7},{5,6}},
    {{0,3},{1,2},{4,8},{5,7}},
    {{0,4},{1,3},{5,8},{6,7}},
    {{0,5},{1,4},{2,3},{6,8}},
    {{0,6},{1,5},{2,4},{7,8}},
    {{0,7},{1,6},{2,5},{3,4}},
    {{0,8},{1,7},{2,6},{3,5}},
};

// ---------------- helpers ----------------
__device__ __forceinline__ void gridSyncAll(unsigned nblocks) {
    __threadfence();
    __syncthreads();
    if (threadIdx.x == 0) {
        unsigned e0 = *(volatile unsigned*)&g_bar_epoch;
        unsigned my = atomicAdd(&g_bar_count, 1u);
        if (my == nblocks - 1u) {
            g_bar_count = 0u;
            __threadfence();
            atomicAdd(&g_bar_epoch, 1u);
        } else {
            while (*(volatile unsigned*)&g_bar_epoch == e0) { __nanosleep(64); }
        }
    }
    __syncthreads();
}

__device__ __forceinline__ void workerSync() {
    __threadfence();
    __syncthreads();
    if (threadIdx.x == 0) {
        unsigned e0 = *(volatile unsigned*)&g_be2;
        unsigned my = atomicAdd(&g_bc2, 1u);
        if (my == P3_WORKERS - 1u) {
            g_bc2 = 0u;
            __threadfence();
            atomicAdd(&g_be2, 1u);
        } else {
            while (*(volatile unsigned*)&g_be2 == e0) { __nanosleep(64); }
        }
    }
    __syncthreads();
}

__device__ __forceinline__ void blockReduce3(float a, float b, float c,
                                             float* sh48, float* res) {
    #pragma unroll
    for (int o = 16; o > 0; o >>= 1) {
        a += __shfl_down_sync(0xffffffffu, a, o);
        b += __shfl_down_sync(0xffffffffu, b, o);
        c += __shfl_down_sync(0xffffffffu, c, o);
    }
    int lane = threadIdx.x & 31, wid = threadIdx.x >> 5;
    if (lane == 0) { sh48[wid*3+0] = a; sh48[wid*3+1] = b; sh48[wid*3+2] = c; }
    __syncthreads();
    if (threadIdx.x < 3) {
        float s = 0.f;
        #pragma unroll
        for (int i = 0; i < 16; i++) s += sh48[i*3 + threadIdx.x];
        res[threadIdx.x] = s;
    }
    __syncthreads();
}

// tf32 MMA m16n8k8: D += A(16x8) * B(8x8)
__device__ __forceinline__ void mma_tf32(float* d, const uint32_t* a,
                                         uint32_t b0, uint32_t b1) {
    asm volatile(
        "mma.sync.aligned.m16n8k8.row.col.f32.tf32.tf32.f32 "
        "{%0,%1,%2,%3}, {%4,%5,%6,%7}, {%8,%9}, {%0,%1,%2,%3};"
        : "+f"(d[0]), "+f"(d[1]), "+f"(d[2]), "+f"(d[3])
        : "r"(a[0]), "r"(a[1]), "r"(a[2]), "r"(a[3]), "r"(b0), "r"(b1));
}

__device__ __forceinline__ void cp16(float* dst_smem, const float* src) {
    uint32_t d = (uint32_t)__cvta_generic_to_shared(dst_smem);
    asm volatile("cp.async.ca.shared.global [%0], [%1], 16;" :: "r"(d), "l"(src));
}

// ---------------- phase 1: foam recurrence (72 participants, grid padded to 148) ----------------
__global__ void __launch_bounds__(512) k_phase1(
        const int* __restrict__ tokens, const float* __restrict__ E,
        const float* __restrict__ Ws, const float* __restrict__ mdb,
        const float* __restrict__ nsens) {
    int b = blockIdx.x;
    if (b >= P1_BLOCKS) return;        // grid padding (no barrier participation)
    int m = b >> 3, c = b & 7, f = m / NB;
    int e = threadIdx.x;
    bool writer = ((b % 24) == 0);     // blocks 0,24,48 own f=0,1,2 outputs
    __shared__ float xs[64];
    __shared__ float sh48[48];
    __shared__ float res[3];
    __shared__ float bcast[8];

    float w[64];
    const float* Wp = Ws + ((size_t)m*D + c*64)*D + e;
    #pragma unroll
    for (int i = 0; i < 64; i++) w[i] = Wp[(size_t)i*D];

    float mem0 = 0.f, mem1 = 0.f, mem2 = 0.f;
    float decay = 0.f;
    float sens = fabsf(nsens[0]);
    float mdb0 = mdb[0];
    float xin_e = E[(size_t)tokens[0]*D + e];

    for (int t = 0; t < T; t++) {
        if ((e >> 6) == c) xs[e & 63] = xin_e;
        __syncthreads();
        float acc = 0.f;
        #pragma unroll
        for (int i = 0; i < 64; i++) acc = fmaf(xs[i], w[i], acc);
        int buf = (t & 1) * (NF*NB*8*D);
        g_part[buf + (m*8 + c)*D + e] = acc;
        __syncthreads();
        gridSyncAll(P1_BLOCKS);

        if (t == 0) {
            float a = mdb0 - sens;
            decay = 1.f / (1.f + expf(-a));
        }
        float s0 = 0.f, s1 = 0.f, s2 = 0.f;
        #pragma unroll
        for (int cc = 0; cc < 8; cc++) {
            s0 += g_part[buf + ((f*NB + 0)*8 + cc)*D + e];
            s1 += g_part[buf + ((f*NB + 1)*8 + cc)*D + e];
            s2 += g_part[buf + ((f*NB + 2)*8 + cc)*D + e];
        }
        #pragma unroll
        for (int it = 0; it < 3; it++) {
            float mn = (s0 + s1 + s2) * (1.0f/3.0f);
            s0 += 0.3f * (mn - s0);
            s1 += 0.3f * (mn - s1);
            s2 += 0.3f * (mn - s2);
        }
        if (writer) {
            blockReduce3(s0*s0, s1*s1, s2*s2, sh48, res);
            if (e == 0) {
                float nr[3] = {sqrtf(res[0]), sqrtf(res[1]), sqrtf(res[2])};
                float mx = fmaxf(fmaxf(2.f*nr[0], 2.f*nr[1]), 2.f*nr[2]);
                float ex[3], se = 0.f;
                #pragma unroll
                for (int n = 0; n < 3; n++) { ex[n] = expf(2.f*nr[n] - mx); se += ex[n]; }
                #pragma unroll
                for (int n = 0; n < 3; n++) {
                    g_w[(t*NF + f)*NB + n] = ex[n] / se;
                    bcast[n] = 1.f / (nr[n] + 1e-10f);
                }
            }
            __syncthreads();
            float u0 = s0 * bcast[0], u1 = s1 * bcast[1], u2 = s2 * bcast[2];
            g_U[((t*NF + f)*NB + 0)*D + e] = u0;
            g_U[((t*NF + f)*NB + 1)*D + e] = u1;
            g_U[((t*NF + f)*NB + 2)*D + e] = u2;
            int jb = t*9 + f*3;
            g_Ut[e*40 + jb + 0] = u0;
            g_Ut[e*40 + jb + 1] = u1;
            g_Ut[e*40 + jb + 2] = u2;
        }
        mem0 = decay*mem0 + (1.f - decay)*s0;
        mem1 = decay*mem1 + (1.f - decay)*s1;
        mem2 = decay*mem2 + (1.f - decay)*s2;
        if (t < T-1) {
            float x = E[(size_t)tokens[t+1]*D + e];
            float mm = (mem0 + mem1 + mem2) * (1.0f/3.0f);
            blockReduce3(mm*mm, x*mm, x*x, sh48, res);
            if (e == 0) {
                float mn = sqrtf(res[0]) + 1e-10f;
                float xn = sqrtf(res[2]) + 1e-10f;
                float nov = (mn > 1e-8f) ? (1.f - res[1]/(xn*mn)) : 1.f;
                float a = mdb0 - sens * nov;
                bcast[4] = 1.f / (1.f + expf(-a));
            }
            __syncthreads();
            decay = bcast[4];
            xin_e = x + decay*mm;
        }
    }
}

// ---------------- phase 2: tf32 GEMM, 64-col superchunks, double-buffered cp.async ----------------
// 256 blocks x 256 threads. Block: 128 v x 40 j x K=512 in 8 superchunks of 64.
__global__ void __launch_bounds__(256) k_P(const float* __restrict__ E) {
    __shared__ float sbuf[22528];
    __shared__ float wsh[36];
    __shared__ float wred[8][12];
    float* Ps = sbuf;
    int tid = threadIdx.x;
    int wid = tid >> 5, lane = tid & 31;
    int v0 = blockIdx.x * 128;
    if (tid < 36) wsh[tid] = g_w[tid];

    float acc[5][4];
    #pragma unroll
    for (int nt = 0; nt < 5; nt++)
        #pragma unroll
        for (int q = 0; q < 4; q++) acc[nt][q] = 0.f;

    int mbase = wid * 16;
    int arow = lane >> 2, acol = lane & 3;
    int brow = lane & 3,  bcol = lane >> 2;

    auto stage = [&](int sc, int s) {
        int k0 = sc * 64;
        float* Es = sbuf + s*8704;
        float* Us = sbuf + 17408 + s*2560;
        #pragma unroll
        for (int it = 0; it < 8; it++) {
            int flat = it*256 + tid;
            int row = flat >> 4, seg = flat & 15;
            cp16(&Es[row*68 + seg*4], E + (size_t)(v0+row)*D + k0 + seg*4);
        }
        #pragma unroll
        for (int it = 0; it < 3; it++) {
            int flat = it*256 + tid;
            if (flat < 640) {
                int dd = flat / 10, q = flat - dd*10;
                cp16(&Us[dd*40 + q*4], g_Ut + (size_t)(k0+dd)*40 + q*4);
            }
        }
    };

    stage(0, 0);
    asm volatile("cp.async.commit_group;");

    for (int sc = 0; sc < 8; sc++) {
        if (sc < 7) {
            stage(sc+1, (sc+1) & 1);
            asm volatile("cp.async.commit_group;");
            asm volatile("cp.async.wait_group 1;" ::: "memory");
        } else {
            asm volatile("cp.async.wait_group 0;" ::: "memory");
        }
        __syncthreads();
        const uint32_t* EsU = (const uint32_t*)(sbuf + (sc & 1)*8704);
        const uint32_t* UsU = (const uint32_t*)(sbuf + 17408 + (sc & 1)*2560);
        #pragma unroll
        for (int ks = 0; ks < 8; ks++) {
            int kb = ks * 8;
            uint32_t a[4];
            int r = mbase + arow;
            a[0] = EsU[r*68 + kb + acol];
            a[1] = EsU[(r+8)*68 + kb + acol];
            a[2] = EsU[r*68 + kb + acol + 4];
            a[3] = EsU[(r+8)*68 + kb + acol + 4];
            #pragma unroll
            for (int nt = 0; nt < 5; nt++) {
                uint32_t b0 = UsU[(kb + brow)*40 + nt*8 + bcol];
                uint32_t b1 = UsU[(kb + brow + 4)*40 + nt*8 + bcol];
                mma_tf32(acc[nt], a, b0, b1);
            }
        }
        __syncthreads();
    }

    // scatter P fragments to smem: Ps[j][v], stride 132
    #pragma unroll
    for (int nt = 0; nt < 5; nt++) {
        int vr = mbase + arow;
        int jc = nt*8 + acol*2;
        Ps[jc*132 + vr]         = acc[nt][0];
        Ps[(jc+1)*132 + vr]     = acc[nt][1];
        Ps[jc*132 + vr + 8]     = acc[nt][2];
        Ps[(jc+1)*132 + vr + 8] = acc[nt][3];
    }
    __syncthreads();
    // epilogue: warp -> (t = wid>>1, half = wid&1), 2 v per lane
    int t = wid >> 1, half = wid & 1;
    int vb = half*64 + lane*2;
    float vals[12];
    #pragma unroll
    for (int k = 0; k < 12; k++) vals[k] = 0.f;
    float ef[3][2];
    #pragma unroll
    for (int f = 0; f < 3; f++) {
        float z0 = 0.f, z1 = 0.f;
        #pragma unroll
        for (int n = 0; n < 3; n++) {
            int j = t*9 + f*3 + n;
            float2 p = *(const float2*)&Ps[j*132 + vb];
            float ww = wsh[j];
            z0 = fmaf(ww*p.x, p.x, z0);
            z1 = fmaf(ww*p.y, p.y, z1);
        }
        *(float2*)&g_Z[((size_t)(t*3+f))*VOCAB + v0 + vb] = make_float2(z0, z1);
        float e0 = __expf(z0), e1 = __expf(z1);
        ef[f][0] = e0; ef[f][1] = e1;
        vals[f]   = e0 + e1;
        vals[3+f] = e0*z0 + e1*z1;
    }
    #pragma unroll
    for (int q = 0; q < 2; q++) {
        vals[6]  += ef[0][q]*ef[0][q];
        vals[7]  += ef[0][q]*ef[1][q];
        vals[8]  += ef[0][q]*ef[2][q];
        vals[9]  += ef[1][q]*ef[1][q];
        vals[10] += ef[1][q]*ef[2][q];
        vals[11] += ef[2][q]*ef[2][q];
    }
    #pragma unroll
    for (int k = 0; k < 12; k++) {
        #pragma unroll
        for (int o = 16; o > 0; o >>= 1)
            vals[k] += __shfl_down_sync(0xffffffffu, vals[k], o);
    }
    if (lane == 0) {
        #pragma unroll
        for (int k = 0; k < 12; k++) wred[wid][k] = vals[k];
    }
    __syncthreads();
    if (tid < 48) {
        int t2 = tid / 12, k = tid % 12;
        g_red5[(t2*KP_BLOCKS + blockIdx.x)*12 + k] = wred[t2*2][k] + wred[t2*2+1][k];
    }
}

// ---------------- phase 3: weights -> (Jacobi || token+rho), 132 participants, grid 148 ----------------
__global__ void __launch_bounds__(512) k_phase3(
        float* __restrict__ out_tok, float* __restrict__ out_d,
        float* __restrict__ out_rho, float* __restrict__ out_w,
        float* __restrict__ out_S, float* __restrict__ out_H,
        float* __restrict__ out_F, const float* __restrict__ mt) {
    int b = blockIdx.x;
    if (b >= P3_PART) return;          // grid padding
    int tid = threadIdx.x;
    int w = tid >> 5, lane = tid & 31;
    bool jac = (b < T);

    __shared__ float red[12];
    __shared__ float gram[45];
    __shared__ float As[81];
    __shared__ float csh[4], ssh[4];
    __shared__ unsigned sE2;

    if (jac && tid == 0) sE2 = *(volatile unsigned*)&g_be2;

    // ===== stage A1: reductions + meta weights (blocks 0..3) =====
    if (jac) {
        int t = b;
        if (w < 12) {
            float s = 0.f;
            for (int i = lane; i < KP_BLOCKS; i += 32) s += g_red5[(t*KP_BLOCKS + i)*12 + w];
            #pragma unroll
            for (int o = 16; o > 0; o >>= 1) s += __shfl_down_sync(0xffffffffu, s, o);
            if (lane == 0) red[w] = s;
        }
        for (int pr = w; pr < 45; pr += 16) {
            int i = 0, rem = pr;
            while (rem > i) { rem -= (i + 1); i++; }
            int j = rem;
            float s = 0.f;
            const float* ui = g_U + (size_t)(t*9 + i)*D;
            const float* uj = g_U + (size_t)(t*9 + j)*D;
            for (int e = lane; e < D; e += 32) s += ui[e]*uj[e];
            #pragma unroll
            for (int o = 16; o > 0; o >>= 1) s += __shfl_down_sync(0xffffffffu, s, o);
            if (lane == 0) gram[pr] = s;
        }
        __syncthreads();
        if (tid == 0) {
            const float MAXENT = logf(32768.0f);
            float S[3]  = { red[0], red[1], red[2] };
            float Tm[3] = { red[3], red[4], red[5] };
            float G00 = red[6], G01 = red[7], G02 = red[8];
            float G11 = red[9], G12 = red[10], G22 = red[11];
            float H[3], conc[3], np[3];
            #pragma unroll
            for (int f = 0; f < 3; f++) {
                H[f] = logf(S[f]) - Tm[f]/S[f];
                conc[f] = 1.f - H[f]/MAXENT;
            }
            np[0] = sqrtf(G00)/S[0] + 1e-10f;
            np[1] = sqrtf(G11)/S[1] + 1e-10f;
            np[2] = sqrtf(G22)/S[2] + 1e-10f;
            float A01 = (G01/(S[0]*S[1]))/(np[0]*np[1]);
            float A02 = (G02/(S[0]*S[2]))/(np[0]*np[2]);
            float A12 = (G12/(S[1]*S[2]))/(np[1]*np[2]);
            float agree[3] = { 0.5f*(A01+A02), 0.5f*(A01+A12), 0.5f*(A02+A12) };
            float temp = fmaxf(fabsf(mt[0]), 0.01f);
            float l[3], mx = -1e30f;
            #pragma unroll
            for (int f = 0; f < 3; f++) { l[f] = conc[f]*agree[f]/temp; mx = fmaxf(mx, l[f]); }
            float ex[3], se = 0.f;
            #pragma unroll
            for (int f = 0; f < 3; f++) { ex[f] = expf(l[f]-mx); se += ex[f]; }
            float c9[9];
            #pragma unroll
            for (int f = 0; f < 3; f++) {
                float wt = ex[f]/se;
                out_w[t*3 + f] = wt;
                g_wt[t*3 + f] = wt;
                g_invSf[t*3 + f] = 1.f/S[f];
                #pragma unroll
                for (int n = 0; n < 3; n++) {
                    c9[f*3+n] = wt * g_w[(t*3+f)*3 + n];
                    g_c[t*9 + f*3 + n] = c9[f*3+n];
                }
            }
            for (int i = 0; i < 9; i++)
                for (int j = 0; j < 9; j++) {
                    int a = i > j ? i : j, bb = i > j ? j : i;
                    As[i*9+j] = sqrtf(c9[i]*c9[j]) * gram[a*(a+1)/2 + bb];
                }
        }
        __syncthreads();
    }
    gridSyncAll(P3_PART);   // weights visible to all

    if (!jac) {
        // ===== workers: stage B then stage C =====
        __shared__ float sh6[6];
        __shared__ float wredB[32];
        __shared__ float sred[2];
        __shared__ float Us[9][512];
        __shared__ float cs[9];
        int wk = b - T;
        int t = wk >> 5;
        int vblock = wk & 31;
        int v = vblock * 1024 + tid * 2;
        if (tid < 3) {
            sh6[tid]   = g_wt[t*3 + tid];
            sh6[3+tid] = g_invSf[t*3 + tid];
        }
        __syncthreads();
        float z0 = 0.f, z1 = 0.f;
        #pragma unroll
        for (int f = 0; f < 3; f++) {
            size_t idx = ((size_t)(t*3+f))*VOCAB + v;
            float2 zf = *(const float2*)&g_Z[idx];
            float wf = sh6[f], isf = sh6[3+f];
            z0 = fmaf(wf, zf.x, z0);
            z1 = fmaf(wf, zf.y, z1);
            *(float2*)&out_d[idx] = make_float2(__expf(zf.x)*isf, __expf(zf.y)*isf);
        }
        float e0 = __expf(z0), e1 = __expf(z1);
        float r0 = e0 + e1;
        float r1 = e0*z0 + e1*z1;
        #pragma unroll
        for (int o = 16; o > 0; o >>= 1) {
            r0 += __shfl_down_sync(0xffffffffu, r0, o);
            r1 += __shfl_down_sync(0xffffffffu, r1, o);
        }
        if (lane == 0) { wredB[w*2] = r0; wredB[w*2+1] = r1; }
        __syncthreads();
        if (tid < 2) {
            float s = 0.f;
            #pragma unroll
            for (int w2 = 0; w2 < 16; w2++) s += wredB[w2*2 + tid];
            g_red7[(t*32 + vblock)*2 + tid] = s;
        }
        workerSync();

        // stage C
        if (tid < 64) {
            int k = tid >> 5, i = tid & 31;
            float val = g_red7[(t*32 + i)*2 + k];
            #pragma unroll
            for (int o = 16; o > 0; o >>= 1) val += __shfl_down_sync(0xffffffffu, val, o);
            if (i == 0) sred[k] = val;
        }
        #pragma unroll
        for (int k = 0; k < 9; k++) Us[k][tid] = g_U[(size_t)(t*9 + k)*D + tid];
        if (tid < 9) cs[tid] = g_c[t*9 + tid];
        __syncthreads();
        float sInv = __fdividef(1.f, sred[0]);
        *(float2*)&out_tok[(size_t)t*VOCAB + v] = make_float2(e0*sInv, e1*sInv);
        int i0 = vblock * 16;
        #pragma unroll
        for (int ii = 0; ii < 16; ii++) {
            int i = i0 + ii;
            float a = 0.f;
            #pragma unroll
            for (int k = 0; k < 9; k++) a = fmaf(cs[k]*Us[k][i], Us[k][tid], a);
            out_rho[((size_t)t*D + i)*D + tid] = a;
        }
    } else {
        // ===== Jacobi blocks: eigen (concurrent with workers) + S/H/F =====
        int t = b;
        if (w == 0) {
            for (int round = 0; round < 9*JAC_SWEEPS; round++) {
                int r = round % 9;
                if (lane < 4) {
                    int p = c_pairs[r][lane][0], q = c_pairs[r][lane][1];
                    float apq = As[p*9+q];
                    float cc = 1.f, ss = 0.f;
                    if (fabsf(apq) > 1e-20f) {
                        float theta = __fdividef(As[q*9+q] - As[p*9+p], 2.f*apq);
                        float tt = __fdividef(copysignf(1.f, theta),
                                   fabsf(theta) + __fsqrt_rn(theta*theta + 1.f));
                        cc = rsqrtf(tt*tt + 1.f);
                        ss = tt*cc;
                    }
                    csh[lane] = cc; ssh[lane] = ss;
                }
                __syncwarp();
                {
                    int k = lane & 3, i = lane >> 2;
                    int p = c_pairs[r][k][0], q = c_pairs[r][k][1];
                    float cc = csh[k], ss = ssh[k];
                    float aip = As[i*9+p], aiq = As[i*9+q];
                    As[i*9+p] = cc*aip - ss*aiq;
                    As[i*9+q] = ss*aip + cc*aiq;
                    if (lane < 4) {
                        int p2 = c_pairs[r][lane][0], q2 = c_pairs[r][lane][1];
                        float c2 = csh[lane], s2 = ssh[lane];
                        float a1 = As[8*9+p2], a2 = As[8*9+q2];
                        As[8*9+p2] = c2*a1 - s2*a2;
                        As[8*9+q2] = s2*a1 + c2*a2;
                    }
                }
                __syncwarp();
                {
                    int k = lane & 3, j = lane >> 2;
                    int p = c_pairs[r][k][0], q = c_pairs[r][k][1];
                    float cc = csh[k], ss = ssh[k];
                    float apj = As[p*9+j], aqj = As[q*9+j];
                    As[p*9+j] = cc*apj - ss*aqj;
                    As[q*9+j] = ss*apj + cc*aqj;
                    if (lane < 4) {
                        int p2 = c_pairs[r][lane][0], q2 = c_pairs[r][lane][1];
                        float c2 = csh[lane], s2 = ssh[lane];
                        float a1 = As[p2*9+8], a2 = As[q2*9+8];
                        As[p2*9+8] = c2*a1 - s2*a2;
                        As[q2*9+8] = s2*a1 + c2*a2;
                    }
                }
                __syncwarp();
            }
        }
        __syncthreads();
        if (tid == 0) {
            float lam[9], sum = 503.0f * 1e-12f;
            for (int i = 0; i < 9; i++) { lam[i] = fmaxf(As[i*9+i], 1e-12f); sum += lam[i]; }
            float inv = __fdividef(1.f, sum), Sr = 0.f;
            for (int i = 0; i < 9; i++) {
                float pp = lam[i]*inv;
                Sr -= pp * fmaxf(__logf(pp), -100.f);
            }
            float pz = 1e-12f*inv;
            Sr -= 503.f * pz * fmaxf(__logf(pz), -100.f);
            out_S[t] = Sr;
            // wait for workers' stage-B sums
            while (*(volatile unsigned*)&g_be2 == sE2) { __nanosleep(64); }
            float S = 0.f, Tm = 0.f;
            for (int i = 0; i < 32; i++) {
                S  += g_red7[(t*32 + i)*2 + 0];
                Tm += g_red7[(t*32 + i)*2 + 1];
            }
            float H = __logf(S) - __fdividef(Tm, S);
            out_H[t] = H;
            out_F[t] = H - Sr;
        }
    }
}

// ---------------- launch ----------------
extern "C" void kernel_launch(void* const* d_in, const int* in_sizes, int n_in,
                              void* d_out, int out_size) {
    (void)in_sizes; (void)n_in; (void)out_size;
    const int*   tokens = (const int*)d_in[0];
    const float* E      = (const float*)d_in[1];
    const float* Ws     = (const float*)d_in[2];
    const float* mt     = (const float*)d_in[3];
    const float* mdb    = (const float*)d_in[4];
    const float* ns     = (const float*)d_in[5];

    float* out     = (float*)d_out;
    float* out_tok = out;                         // [4, 32768]
    float* out_rho = out_tok + T*VOCAB;           // [4, 512, 512]
    float* out_w   = out_rho + (size_t)T*D*D;     // [4, 3]
    float* out_S   = out_w + T*NF;                // [4]
    float* out_H   = out_S + T;                   // [4]
    float* out_F   = out_H + T;                   // [4]
    float* out_d   = out_F + T;                   // [4, 3, 32768]

    k_phase1<<<P1_GRID, D>>>(tokens, E, Ws, mdb, ns);
    k_P<<<KP_BLOCKS, 256>>>(E);
    k_phase3<<<P3_GRID, 512>>>(out_tok, out_d, out_rho, out_w, out_S,
                               out_H, out_F, mt);
}